// round 4
// baseline (speedup 1.0000x reference)
#include <cuda_runtime.h>
#include <cstdint>

#define NNODES 4096
#define NEDGES 131072
#define IN_CH 512
#define E_CH 64
#define HID 256
#define OUTD 16
#define NB_E 5      // K + J
#define NB_Z 3      // J
#define REWEIGHT 0.6454972243679028f  // sqrt((64+256)/(512+256))

// ---------------- scratch (static device memory; referenced ONLY inside kernels)
__device__ int   g_idx64;
__device__ int   g_deg[NNODES];
__device__ int   g_rowptr[NNODES + 1];
__device__ int   g_cursor[NNODES];
__device__ float g_dinv[NNODES];
__device__ int   g_col[NEDGES];
__device__ float g_w[NEDGES];
__device__ float g_h1[NNODES * HID];              // x@W1
__device__ float g_hx[NNODES * HID];              // hidden_x (post-prop, relu)
__device__ float g_he[NB_E * NNODES * HID];       // REWEIGHT * e_noise @ We (pre-prop)
__device__ float g_hide[NB_E * NNODES * HID];     // hidden_e (post-prop)
__device__ float g_t[NB_E * NNODES * 32];         // hidden1 @ [Wmu|Wsig]
__device__ float g_acc[8];                        // [0]=sumsq(hx), [1..5]=sumsq(he_b)

// output layout (concat of returned tuple, f32)
#define OFF_ADJ 0ull
#define OFF_MU  (OFF_ADJ + 3ull * NNODES * NNODES)
#define OFF_SIG (OFF_MU  + (unsigned long long)NB_E * NNODES * OUTD)
#define OFF_Z   (OFF_SIG + (unsigned long long)NB_E * NNODES * OUTD)
#define OFF_ZS  (OFF_Z   + (unsigned long long)NB_Z * NNODES * OUTD)
#define OFF_EPS (OFF_ZS  + (unsigned long long)NB_Z * NNODES * OUTD)
#define OFF_RK  (OFF_EPS + (unsigned long long)NB_Z * NNODES * OUTD)
#define OFF_SNR (OFF_RK + 16ull)

// ---------------- edge accessors (int32 vs int64 little-endian) ---------------
__device__ __forceinline__ int edge_src(const int* ei, int i, int w64) {
    return w64 ? ei[2 * i] : ei[i];
}
__device__ __forceinline__ int edge_dst(const int* ei, int i, int w64) {
    return w64 ? ei[2 * (NEDGES + i)] : ei[NEDGES + i];
}

__global__ void detect_kernel(const int* __restrict__ ei) {
    if (threadIdx.x == 0) {
        int nz = 0;
        for (int k = 1; k < 128; k += 2) nz += (ei[k] != 0);
        g_idx64 = (nz == 0) ? 1 : 0;
    }
}

// ---------------- small setup kernels ----------------
__global__ void zero_kernel() {
    int i = blockIdx.x * blockDim.x + threadIdx.x;
    if (i < NNODES) g_deg[i] = 0;
    if (i < 8) g_acc[i] = 0.0f;
}

__global__ void deg_count_kernel(const int* __restrict__ ei) {
    int i = blockIdx.x * blockDim.x + threadIdx.x;
    int w64 = g_idx64;
    if (i < NEDGES) atomicAdd(&g_deg[edge_dst(ei, i, w64)], 1);
}

__global__ void dinv_kernel() {
    int i = blockIdx.x * blockDim.x + threadIdx.x;
    if (i < NNODES) g_dinv[i] = rsqrtf((float)g_deg[i] + 1.0f);
}

// single-block exclusive scan of g_deg (N=4096, 1024 threads x 4)
__global__ void scan_kernel() {
    __shared__ int sums[32];
    int tid = threadIdx.x;
    int base = tid * 4;
    int v[4];
    int s = 0;
#pragma unroll
    for (int i = 0; i < 4; i++) { v[i] = g_deg[base + i]; s += v[i]; }
    int lane = tid & 31, wid = tid >> 5;
    int ss = s;
#pragma unroll
    for (int o = 1; o < 32; o <<= 1) {
        int t = __shfl_up_sync(0xffffffffu, ss, o);
        if (lane >= o) ss += t;
    }
    if (lane == 31) sums[wid] = ss;
    __syncthreads();
    if (wid == 0) {
        int w = sums[lane];
#pragma unroll
        for (int o = 1; o < 32; o <<= 1) {
            int t = __shfl_up_sync(0xffffffffu, w, o);
            if (lane >= o) w += t;
        }
        sums[lane] = w;
    }
    __syncthreads();
    int excl = ss - s + (wid > 0 ? sums[wid - 1] : 0);
    int run = excl;
#pragma unroll
    for (int i = 0; i < 4; i++) {
        g_rowptr[base + i] = run;
        g_cursor[base + i] = run;
        run += v[i];
    }
    if (tid == 1023) g_rowptr[NNODES] = run;
}

__global__ void csr_fill_kernel(const int* __restrict__ ei) {
    int i = blockIdx.x * blockDim.x + threadIdx.x;
    if (i >= NEDGES) return;
    int w64 = g_idx64;
    int s = edge_src(ei, i, w64);
    int d = edge_dst(ei, i, w64);
    int pos = atomicAdd(&g_cursor[d], 1);
    g_col[pos] = s;
    g_w[pos] = g_dinv[s] * g_dinv[d];
}

// ---------------- SGEMM into g_h1 (DST=0) or g_he (DST=1); scratch via symbols -
template <int DST>
__global__ __launch_bounds__(256) void sgemm128(const float* __restrict__ A,
                                                const float* __restrict__ B,
                                                int K, float scale) {
    const int BM = 128, BN = 128, BK = 8, TM = 8, TN = 8;
    const int Nc = HID;
    float* C = (DST == 0) ? g_h1 : g_he;
    __shared__ float As[BK][BM];
    __shared__ float Bs[BK][BN];
    int tid = threadIdx.x;
    const float* Ab = A + (size_t)blockIdx.y * BM * K;
    const float* Bb = B + blockIdx.x * BN;
    float* Cb = C + (size_t)blockIdx.y * BM * Nc + blockIdx.x * BN;

    int aRow = tid >> 1;
    int aCol = (tid & 1) * 4;
    int bRow = tid >> 5;
    int bCol = (tid & 31) * 4;
    int ty = tid >> 4, tx = tid & 15;

    float acc[TM][TN] = {};
    for (int k0 = 0; k0 < K; k0 += BK) {
        float4 a4 = *reinterpret_cast<const float4*>(Ab + (size_t)aRow * K + k0 + aCol);
        float4 b4 = *reinterpret_cast<const float4*>(Bb + (size_t)(k0 + bRow) * Nc + bCol);
        __syncthreads();
        As[aCol + 0][aRow] = a4.x;
        As[aCol + 1][aRow] = a4.y;
        As[aCol + 2][aRow] = a4.z;
        As[aCol + 3][aRow] = a4.w;
        *reinterpret_cast<float4*>(&Bs[bRow][bCol]) = b4;
        __syncthreads();
#pragma unroll
        for (int kk = 0; kk < BK; kk++) {
            float ra[TM], rb[TN];
#pragma unroll
            for (int i = 0; i < TM; i++) ra[i] = As[kk][ty * TM + i];
#pragma unroll
            for (int j = 0; j < TN; j++) rb[j] = Bs[kk][tx * TN + j];
#pragma unroll
            for (int i = 0; i < TM; i++)
#pragma unroll
                for (int j = 0; j < TN; j++) acc[i][j] = fmaf(ra[i], rb[j], acc[i][j]);
        }
    }
#pragma unroll
    for (int i = 0; i < TM; i++) {
        float* crow = Cb + (size_t)(ty * TM + i) * Nc + tx * TN;
#pragma unroll
        for (int j = 0; j < TN; j += 4) {
            float4 v;
            v.x = acc[i][j] * scale; v.y = acc[i][j + 1] * scale;
            v.z = acc[i][j + 2] * scale; v.w = acc[i][j + 3] * scale;
            *reinterpret_cast<float4*>(crow + j) = v;
        }
    }
}

// ---------------- 256-ch GCN propagation; WHICH=0: g_h1->g_hx (relu), 1: g_he->g_hide
template <int WHICH>
__global__ __launch_bounds__(256) void prop256_kernel(const float* __restrict__ bias) {
    const float* h = (WHICH == 0) ? g_h1 : g_he;
    float* out = (WHICH == 0) ? g_hx : g_hide;
    int n = blockIdx.x;
    const float* hb = h + (size_t)blockIdx.y * NNODES * HID;
    float* ob = out + (size_t)blockIdx.y * NNODES * HID;
    int c = threadIdx.x;
    int start = g_rowptr[n], end = g_rowptr[n + 1];
    float d = g_dinv[n];
    float acc = hb[(size_t)n * HID + c] * d * d;
    for (int j = start; j < end; j++)
        acc = fmaf(g_w[j], hb[(size_t)g_col[j] * HID + c], acc);
    acc += bias[c];
    if (WHICH == 0) acc = fmaxf(acc, 0.0f);
    ob[(size_t)n * HID + c] = acc;
}

// ---------------- sum of squares reductions (all symbol-internal) --------------
__global__ void sumsq_kernel() {
    const float* a = (blockIdx.y == 0) ? g_hx
                                       : g_hide + (size_t)(blockIdx.y - 1) * NNODES * HID;
    const int n = NNODES * HID;
    float s = 0.0f;
    for (int i = blockIdx.x * blockDim.x + threadIdx.x; i < n; i += gridDim.x * blockDim.x) {
        float v = a[i];
        s = fmaf(v, v, s);
    }
#pragma unroll
    for (int o = 16; o > 0; o >>= 1) s += __shfl_down_sync(0xffffffffu, s, o);
    __shared__ float ws[32];
    int lane = threadIdx.x & 31, wid = threadIdx.x >> 5;
    if (lane == 0) ws[wid] = s;
    __syncthreads();
    if (wid == 0) {
        s = (lane < (blockDim.x >> 5)) ? ws[lane] : 0.0f;
#pragma unroll
        for (int o = 16; o > 0; o >>= 1) s += __shfl_down_sync(0xffffffffu, s, o);
        if (lane == 0) atomicAdd(&g_acc[blockIdx.y], s);
    }
}

// ---- t[r,c] = (hx[n,:]+hide[r,:]) @ (c<16 ? Wmu[:,c] : Wsig[:,c-16]); 8 rows/blk
__global__ __launch_bounds__(256) void proj_kernel(const float* __restrict__ Wmu,
                                                   const float* __restrict__ Wsig) {
    int r0 = blockIdx.x * 8;
    __shared__ float s[8 * 256];
    int tid = threadIdx.x;
    for (int i = tid; i < 8 * 256; i += 256) {
        int lr = i >> 8, k = i & 255;
        int r = r0 + lr;
        int n = r & (NNODES - 1);
        s[i] = g_hx[(size_t)n * HID + k] + g_hide[(size_t)r * HID + k];
    }
    __syncthreads();
    int lr = tid >> 5, c = tid & 31;
    const float* W = (c < 16) ? Wmu : Wsig;
    int cc = c & 15;
    float acc = 0.0f;
    const float* srow = &s[lr * 256];
#pragma unroll 8
    for (int k = 0; k < 256; k++) acc = fmaf(srow[k], W[k * 16 + cc], acc);
    g_t[(size_t)(r0 + lr) * 32 + c] = acc;
}

// ---------------- 32-channel propagation -> mu/sigma directly to d_out --------
__global__ void prop32_kernel(const float* __restrict__ bmu,
                              const float* __restrict__ bsig,
                              float* __restrict__ out) {
    int warp = (blockIdx.x * blockDim.x + threadIdx.x) >> 5;
    int lane = threadIdx.x & 31;
    if (warp >= NB_E * NNODES) return;
    int b = warp >> 12;
    int n = warp & (NNODES - 1);
    const float* tb = g_t + (size_t)b * NNODES * 32;
    float d = g_dinv[n];
    float acc = tb[(size_t)n * 32 + lane] * d * d;
    int start = g_rowptr[n], end = g_rowptr[n + 1];
    for (int j = start; j < end; j++)
        acc = fmaf(g_w[j], tb[(size_t)g_col[j] * 32 + lane], acc);
    size_t base = ((size_t)b * NNODES + n) * OUTD;
    if (lane < 16) out[OFF_MU + base + lane] = acc + bmu[lane];
    else           out[OFF_SIG + base + (lane - 16)] = acc + bsig[lane - 16];
}

// ---------------- z = eps * exp(0.5*logvar) + mu -------------------------------
__global__ void z_kernel(const float* __restrict__ eps, float* __restrict__ out) {
    int i = blockIdx.x * blockDim.x + threadIdx.x;
    const int total = NB_Z * NNODES * OUTD;
    if (i >= total) return;
    int b = i / (NNODES * OUTD);
    int rem = i - b * (NNODES * OUTD);
    size_t src = (size_t)(b + 2) * NNODES * OUTD + rem;   // K = 2
    float lv = out[OFF_SIG + src];
    float m = out[OFF_MU + src];
    float e = eps[i];
    float zv = fmaf(e, expf(0.5f * lv), m);
    out[OFF_Z + i] = zv;
    out[OFF_ZS + i] = zv;
    out[OFF_EPS + i] = e;
}

__global__ void finalize_kernel(const float* __restrict__ rk_lgt, float* __restrict__ out) {
    int t = threadIdx.x;
    if (t < 5) out[OFF_SNR + t] = g_acc[0] / g_acc[1 + t];
    if (t < 16) out[OFF_RK + t] = sqrtf(1.0f / (1.0f + expf(-rk_lgt[t])));
}

// ---------------- FMA-only sigmoid (no MUFU) -----------------------------------
__device__ __forceinline__ float fast_sigmoid(float x) {
    x = fminf(fmaxf(x, -80.0f), 80.0f);
    float t = x * -1.4426950408889634f;          // 2^t = e^{-x}
    float z = t + 12582912.0f;                   // round to nearest int (magic)
    int n = __float_as_int(z);                   // low bits hold the integer; <<23 wraps clean
    float f = t - (z - 12582912.0f);             // f in [-0.5, 0.5]
    float p = 1.3333558146e-3f;
    p = fmaf(p, f, 9.6181291076e-3f);
    p = fmaf(p, f, 5.5504108665e-2f);
    p = fmaf(p, f, 2.4022650696e-1f);
    p = fmaf(p, f, 6.9314718056e-1f);
    p = fmaf(p, f, 1.0f);
    float u = __int_as_float(__float_as_int(p) + (n << 23));  // e^{-x}
    float d = 1.0f + u;
    float r = __int_as_float(0x7EF311C3 - __float_as_int(d)); // ~rcp
    r = r * fmaf(-d, r, 2.0f);
    r = r * fmaf(-d, r, 2.0f);
    r = r * fmaf(-d, r, 2.0f);
    return r;
}

// ---------------- adj = sigmoid(z @ z^T), 64x64 tile per block ------------------
__global__ __launch_bounds__(256) void adj_kernel(float* __restrict__ out) {
    const float* zb = out + OFF_Z + (size_t)blockIdx.z * NNODES * OUTD;
    float* ab = out + OFF_ADJ + (size_t)blockIdx.z * NNODES * NNODES;
    __shared__ float zi[64][17];
    __shared__ float zj[64][17];
    int i0 = blockIdx.y * 64, j0 = blockIdx.x * 64;
    int tid = threadIdx.x;
    for (int t = tid; t < 1024; t += 256) {
        int r = t >> 4, k = t & 15;
        zi[r][k] = zb[(size_t)(i0 + r) * 16 + k];
        zj[r][k] = zb[(size_t)(j0 + r) * 16 + k];
    }
    __syncthreads();
    int tx = tid & 15, ty = tid >> 4;
    float acc[4][4] = {};
#pragma unroll
    for (int k = 0; k < 16; k++) {
        float a[4], b[4];
#pragma unroll
        for (int ii = 0; ii < 4; ii++) a[ii] = zi[ty * 4 + ii][k];
#pragma unroll
        for (int jj = 0; jj < 4; jj++) b[jj] = zj[tx * 4 + jj][k];
#pragma unroll
        for (int ii = 0; ii < 4; ii++)
#pragma unroll
            for (int jj = 0; jj < 4; jj++) acc[ii][jj] = fmaf(a[ii], b[jj], acc[ii][jj]);
    }
#pragma unroll
    for (int ii = 0; ii < 4; ii++) {
        float4 v;
        v.x = fast_sigmoid(acc[ii][0]);
        v.y = fast_sigmoid(acc[ii][1]);
        v.z = fast_sigmoid(acc[ii][2]);
        v.w = fast_sigmoid(acc[ii][3]);
        *reinterpret_cast<float4*>(&ab[(size_t)(i0 + ty * 4 + ii) * NNODES + j0 + tx * 4]) = v;
    }
}

// =================================================================================
extern "C" void kernel_launch(void* const* d_in, const int* in_sizes, int n_in,
                              void* d_out, int out_size) {
    (void)in_sizes; (void)n_in; (void)out_size;
    const float* x       = (const float*)d_in[0];
    const int*   ei      = (const int*)d_in[1];
    const float* e_noise = (const float*)d_in[2];
    const float* eps     = (const float*)d_in[3];
    const float* W1      = (const float*)d_in[4];
    const float* b1      = (const float*)d_in[5];
    const float* We      = (const float*)d_in[6];
    const float* be      = (const float*)d_in[7];
    const float* Wmu     = (const float*)d_in[8];
    const float* bmu     = (const float*)d_in[9];
    const float* Wsig    = (const float*)d_in[10];
    const float* bsig    = (const float*)d_in[11];
    const float* rk_lgt  = (const float*)d_in[12];
    float* out = (float*)d_out;

    // graph setup
    detect_kernel<<<1, 32>>>(ei);
    zero_kernel<<<16, 256>>>();
    deg_count_kernel<<<NEDGES / 256, 256>>>(ei);
    dinv_kernel<<<16, 256>>>();
    scan_kernel<<<1, 1024>>>();
    csr_fill_kernel<<<NEDGES / 256, 256>>>(ei);

    // feature GEMMs (scratch via symbols INSIDE the kernels)
    sgemm128<0><<<dim3(HID / 128, NNODES / 128), 256>>>(x, W1, IN_CH, 1.0f);
    sgemm128<1><<<dim3(HID / 128, NB_E * NNODES / 128), 256>>>(e_noise, We, E_CH, REWEIGHT);

    // 256-channel propagations
    prop256_kernel<0><<<dim3(NNODES, 1), 256>>>(b1);
    prop256_kernel<1><<<dim3(NNODES, NB_E), 256>>>(be);

    // SNR reductions
    sumsq_kernel<<<dim3(128, 6), 256>>>();

    // mu/sigma: project to 32 channels, propagate 32 channels
    proj_kernel<<<NB_E * NNODES / 8, 256>>>(Wmu, Wsig);
    prop32_kernel<<<NB_E * NNODES * 32 / 256, 256>>>(bmu, bsig, out);

    // z / eps / rk / snr
    z_kernel<<<(NB_Z * NNODES * OUTD + 255) / 256, 256>>>(eps, out);
    finalize_kernel<<<1, 32>>>(rk_lgt, out);

    // decoder
    adj_kernel<<<dim3(NNODES / 64, NNODES / 64, NB_Z), 256>>>(out);
}

// round 5
// speedup vs baseline: 1.0016x; 1.0016x over previous
#include <cuda_runtime.h>
#include <cstdint>

#define NNODES 4096
#define NEDGES 131072
#define IN_CH 512
#define E_CH 64
#define HID 256
#define OUTD 16
#define NB_E 5      // K + J
#define NB_Z 3      // J
#define REWEIGHT 0.6454972243679028f  // sqrt((64+256)/(512+256))

// ---------------- scratch (static device memory; referenced ONLY inside kernels)
__device__ int   g_idx64;
__device__ int   g_deg[NNODES];
__device__ int   g_rowptr[NNODES + 1];
__device__ int   g_cursor[NNODES];
__device__ float g_dinv[NNODES];
__device__ int   g_col[NEDGES];
__device__ float g_w[NEDGES];
__device__ float g_h1[NNODES * HID];              // x@W1
__device__ float g_hx[NNODES * HID];              // hidden_x (post-prop, relu)
__device__ float g_he[NB_E * NNODES * HID];       // REWEIGHT * e_noise @ We (pre-prop)
__device__ float g_hide[NB_E * NNODES * HID];     // hidden_e (post-prop)
__device__ float g_t[NB_E * NNODES * 32];         // hidden1 @ [Wmu|Wsig]
__device__ float g_acc[8];                        // [0]=sumsq(hx), [1..5]=sumsq(he_b)

// output layout (concat of returned tuple, f32)
#define OFF_ADJ 0ull
#define OFF_MU  (OFF_ADJ + 3ull * NNODES * NNODES)
#define OFF_SIG (OFF_MU  + (unsigned long long)NB_E * NNODES * OUTD)
#define OFF_Z   (OFF_SIG + (unsigned long long)NB_E * NNODES * OUTD)
#define OFF_ZS  (OFF_Z   + (unsigned long long)NB_Z * NNODES * OUTD)
#define OFF_EPS (OFF_ZS  + (unsigned long long)NB_Z * NNODES * OUTD)
#define OFF_RK  (OFF_EPS + (unsigned long long)NB_Z * NNODES * OUTD)
#define OFF_SNR (OFF_RK + 16ull)

// ---------------- edge accessors (int32 vs int64 little-endian) ---------------
__device__ __forceinline__ int edge_src(const int* ei, int i, int w64) {
    return w64 ? ei[2 * i] : ei[i];
}
__device__ __forceinline__ int edge_dst(const int* ei, int i, int w64) {
    return w64 ? ei[2 * (NEDGES + i)] : ei[NEDGES + i];
}

__global__ void detect_kernel(const int* __restrict__ ei) {
    if (threadIdx.x == 0) {
        int nz = 0;
        for (int k = 1; k < 128; k += 2) nz += (ei[k] != 0);
        g_idx64 = (nz == 0) ? 1 : 0;
    }
}

// ---------------- small setup kernels ----------------
__global__ void zero_kernel() {
    int i = blockIdx.x * blockDim.x + threadIdx.x;
    if (i < NNODES) g_deg[i] = 0;
    if (i < 8) g_acc[i] = 0.0f;
}

__global__ void deg_count_kernel(const int* __restrict__ ei) {
    int i = blockIdx.x * blockDim.x + threadIdx.x;
    int w64 = g_idx64;
    if (i < NEDGES) atomicAdd(&g_deg[edge_dst(ei, i, w64)], 1);
}

__global__ void dinv_kernel() {
    int i = blockIdx.x * blockDim.x + threadIdx.x;
    if (i < NNODES) g_dinv[i] = rsqrtf((float)g_deg[i] + 1.0f);
}

// single-block exclusive scan of g_deg (N=4096, 1024 threads x 4)
__global__ void scan_kernel() {
    __shared__ int sums[32];
    int tid = threadIdx.x;
    int base = tid * 4;
    int v[4];
    int s = 0;
#pragma unroll
    for (int i = 0; i < 4; i++) { v[i] = g_deg[base + i]; s += v[i]; }
    int lane = tid & 31, wid = tid >> 5;
    int ss = s;
#pragma unroll
    for (int o = 1; o < 32; o <<= 1) {
        int t = __shfl_up_sync(0xffffffffu, ss, o);
        if (lane >= o) ss += t;
    }
    if (lane == 31) sums[wid] = ss;
    __syncthreads();
    if (wid == 0) {
        int w = sums[lane];
#pragma unroll
        for (int o = 1; o < 32; o <<= 1) {
            int t = __shfl_up_sync(0xffffffffu, w, o);
            if (lane >= o) w += t;
        }
        sums[lane] = w;
    }
    __syncthreads();
    int excl = ss - s + (wid > 0 ? sums[wid - 1] : 0);
    int run = excl;
#pragma unroll
    for (int i = 0; i < 4; i++) {
        g_rowptr[base + i] = run;
        g_cursor[base + i] = run;
        run += v[i];
    }
    if (tid == 1023) g_rowptr[NNODES] = run;
}

__global__ void csr_fill_kernel(const int* __restrict__ ei) {
    int i = blockIdx.x * blockDim.x + threadIdx.x;
    if (i >= NEDGES) return;
    int w64 = g_idx64;
    int s = edge_src(ei, i, w64);
    int d = edge_dst(ei, i, w64);
    int pos = atomicAdd(&g_cursor[d], 1);
    g_col[pos] = s;
    g_w[pos] = g_dinv[s] * g_dinv[d];
}

// ---------------- SGEMM into g_h1 (DST=0) or g_he (DST=1); scratch via symbols -
template <int DST>
__global__ __launch_bounds__(256) void sgemm128(const float* __restrict__ A,
                                                const float* __restrict__ B,
                                                int K, float scale) {
    const int BM = 128, BN = 128, BK = 8, TM = 8, TN = 8;
    const int Nc = HID;
    float* C = (DST == 0) ? g_h1 : g_he;
    __shared__ float As[BK][BM];
    __shared__ float Bs[BK][BN];
    int tid = threadIdx.x;
    const float* Ab = A + (size_t)blockIdx.y * BM * K;
    const float* Bb = B + blockIdx.x * BN;
    float* Cb = C + (size_t)blockIdx.y * BM * Nc + blockIdx.x * BN;

    int aRow = tid >> 1;
    int aCol = (tid & 1) * 4;
    int bRow = tid >> 5;
    int bCol = (tid & 31) * 4;
    int ty = tid >> 4, tx = tid & 15;

    float acc[TM][TN] = {};
    for (int k0 = 0; k0 < K; k0 += BK) {
        float4 a4 = *reinterpret_cast<const float4*>(Ab + (size_t)aRow * K + k0 + aCol);
        float4 b4 = *reinterpret_cast<const float4*>(Bb + (size_t)(k0 + bRow) * Nc + bCol);
        __syncthreads();
        As[aCol + 0][aRow] = a4.x;
        As[aCol + 1][aRow] = a4.y;
        As[aCol + 2][aRow] = a4.z;
        As[aCol + 3][aRow] = a4.w;
        *reinterpret_cast<float4*>(&Bs[bRow][bCol]) = b4;
        __syncthreads();
#pragma unroll
        for (int kk = 0; kk < BK; kk++) {
            float ra[TM], rb[TN];
#pragma unroll
            for (int i = 0; i < TM; i++) ra[i] = As[kk][ty * TM + i];
#pragma unroll
            for (int j = 0; j < TN; j++) rb[j] = Bs[kk][tx * TN + j];
#pragma unroll
            for (int i = 0; i < TM; i++)
#pragma unroll
                for (int j = 0; j < TN; j++) acc[i][j] = fmaf(ra[i], rb[j], acc[i][j]);
        }
    }
#pragma unroll
    for (int i = 0; i < TM; i++) {
        float* crow = Cb + (size_t)(ty * TM + i) * Nc + tx * TN;
#pragma unroll
        for (int j = 0; j < TN; j += 4) {
            float4 v;
            v.x = acc[i][j] * scale; v.y = acc[i][j + 1] * scale;
            v.z = acc[i][j + 2] * scale; v.w = acc[i][j + 3] * scale;
            *reinterpret_cast<float4*>(crow + j) = v;
        }
    }
}

// ---------------- 256-ch GCN propagation; WHICH=0: g_h1->g_hx (relu), 1: g_he->g_hide
template <int WHICH>
__global__ __launch_bounds__(256) void prop256_kernel(const float* __restrict__ bias) {
    const float* h = (WHICH == 0) ? g_h1 : g_he;
    float* out = (WHICH == 0) ? g_hx : g_hide;
    int n = blockIdx.x;
    const float* hb = h + (size_t)blockIdx.y * NNODES * HID;
    float* ob = out + (size_t)blockIdx.y * NNODES * HID;
    int c = threadIdx.x;
    int start = g_rowptr[n], end = g_rowptr[n + 1];
    float d = g_dinv[n];
    float acc = hb[(size_t)n * HID + c] * d * d;
    for (int j = start; j < end; j++)
        acc = fmaf(g_w[j], hb[(size_t)g_col[j] * HID + c], acc);
    acc += bias[c];
    if (WHICH == 0) acc = fmaxf(acc, 0.0f);
    ob[(size_t)n * HID + c] = acc;
}

// ---------------- sum of squares reductions (all symbol-internal) --------------
__global__ void sumsq_kernel() {
    const float* a = (blockIdx.y == 0) ? g_hx
                                       : g_hide + (size_t)(blockIdx.y - 1) * NNODES * HID;
    const int n = NNODES * HID;
    float s = 0.0f;
    for (int i = blockIdx.x * blockDim.x + threadIdx.x; i < n; i += gridDim.x * blockDim.x) {
        float v = a[i];
        s = fmaf(v, v, s);
    }
#pragma unroll
    for (int o = 16; o > 0; o >>= 1) s += __shfl_down_sync(0xffffffffu, s, o);
    __shared__ float ws[32];
    int lane = threadIdx.x & 31, wid = threadIdx.x >> 5;
    if (lane == 0) ws[wid] = s;
    __syncthreads();
    if (wid == 0) {
        s = (lane < (blockDim.x >> 5)) ? ws[lane] : 0.0f;
#pragma unroll
        for (int o = 16; o > 0; o >>= 1) s += __shfl_down_sync(0xffffffffu, s, o);
        if (lane == 0) atomicAdd(&g_acc[blockIdx.y], s);
    }
}

// ---- t[r,c] = (hx[n,:]+hide[r,:]) @ (c<16 ? Wmu[:,c] : Wsig[:,c-16]); 8 rows/blk
__global__ __launch_bounds__(256) void proj_kernel(const float* __restrict__ Wmu,
                                                   const float* __restrict__ Wsig) {
    int r0 = blockIdx.x * 8;
    __shared__ float s[8 * 256];
    int tid = threadIdx.x;
    for (int i = tid; i < 8 * 256; i += 256) {
        int lr = i >> 8, k = i & 255;
        int r = r0 + lr;
        int n = r & (NNODES - 1);
        s[i] = g_hx[(size_t)n * HID + k] + g_hide[(size_t)r * HID + k];
    }
    __syncthreads();
    int lr = tid >> 5, c = tid & 31;
    const float* W = (c < 16) ? Wmu : Wsig;
    int cc = c & 15;
    float acc = 0.0f;
    const float* srow = &s[lr * 256];
#pragma unroll 8
    for (int k = 0; k < 256; k++) acc = fmaf(srow[k], W[k * 16 + cc], acc);
    g_t[(size_t)(r0 + lr) * 32 + c] = acc;
}

// ---------------- 32-channel propagation -> mu/sigma directly to d_out --------
__global__ void prop32_kernel(const float* __restrict__ bmu,
                              const float* __restrict__ bsig,
                              float* __restrict__ out) {
    int warp = (blockIdx.x * blockDim.x + threadIdx.x) >> 5;
    int lane = threadIdx.x & 31;
    if (warp >= NB_E * NNODES) return;
    int b = warp >> 12;
    int n = warp & (NNODES - 1);
    const float* tb = g_t + (size_t)b * NNODES * 32;
    float d = g_dinv[n];
    float acc = tb[(size_t)n * 32 + lane] * d * d;
    int start = g_rowptr[n], end = g_rowptr[n + 1];
    for (int j = start; j < end; j++)
        acc = fmaf(g_w[j], tb[(size_t)g_col[j] * 32 + lane], acc);
    size_t base = ((size_t)b * NNODES + n) * OUTD;
    if (lane < 16) out[OFF_MU + base + lane] = acc + bmu[lane];
    else           out[OFF_SIG + base + (lane - 16)] = acc + bsig[lane - 16];
}

// ---------------- z = eps * exp(0.5*logvar) + mu -------------------------------
__global__ void z_kernel(const float* __restrict__ eps, float* __restrict__ out) {
    int i = blockIdx.x * blockDim.x + threadIdx.x;
    const int total = NB_Z * NNODES * OUTD;
    if (i >= total) return;
    int b = i / (NNODES * OUTD);
    int rem = i - b * (NNODES * OUTD);
    size_t src = (size_t)(b + 2) * NNODES * OUTD + rem;   // K = 2
    float lv = out[OFF_SIG + src];
    float m = out[OFF_MU + src];
    float e = eps[i];
    float zv = fmaf(e, expf(0.5f * lv), m);
    out[OFF_Z + i] = zv;
    out[OFF_ZS + i] = zv;
    out[OFF_EPS + i] = e;
}

__global__ void finalize_kernel(const float* __restrict__ rk_lgt, float* __restrict__ out) {
    int t = threadIdx.x;
    if (t < 5) out[OFF_SNR + t] = g_acc[0] / g_acc[1 + t];
    if (t < 16) out[OFF_RK + t] = sqrtf(1.0f / (1.0f + expf(-rk_lgt[t])));
}

// ---------------- FMA-only sigmoid (no MUFU) -----------------------------------
__device__ __forceinline__ float fast_sigmoid(float x) {
    x = fminf(fmaxf(x, -80.0f), 80.0f);
    float t = x * -1.4426950408889634f;          // 2^t = e^{-x}
    float z = t + 12582912.0f;                   // round to nearest int (magic)
    int n = __float_as_int(z);                   // low bits hold the integer; <<23 wraps clean
    float f = t - (z - 12582912.0f);             // f in [-0.5, 0.5]
    float p = 1.3333558146e-3f;
    p = fmaf(p, f, 9.6181291076e-3f);
    p = fmaf(p, f, 5.5504108665e-2f);
    p = fmaf(p, f, 2.4022650696e-1f);
    p = fmaf(p, f, 6.9314718056e-1f);
    p = fmaf(p, f, 1.0f);
    float u = __int_as_float(__float_as_int(p) + (n << 23));  // e^{-x}
    float d = 1.0f + u;
    float r = __int_as_float(0x7EF311C3 - __float_as_int(d)); // ~rcp
    r = r * fmaf(-d, r, 2.0f);
    r = r * fmaf(-d, r, 2.0f);
    r = r * fmaf(-d, r, 2.0f);
    return r;
}

// ---------------- adj = sigmoid(z @ z^T), 64x64 tile per block ------------------
__global__ __launch_bounds__(256) void adj_kernel(float* __restrict__ out) {
    const float* zb = out + OFF_Z + (size_t)blockIdx.z * NNODES * OUTD;
    float* ab = out + OFF_ADJ + (size_t)blockIdx.z * NNODES * NNODES;
    __shared__ float zi[64][17];
    __shared__ float zj[64][17];
    int i0 = blockIdx.y * 64, j0 = blockIdx.x * 64;
    int tid = threadIdx.x;
    for (int t = tid; t < 1024; t += 256) {
        int r = t >> 4, k = t & 15;
        zi[r][k] = zb[(size_t)(i0 + r) * 16 + k];
        zj[r][k] = zb[(size_t)(j0 + r) * 16 + k];
    }
    __syncthreads();
    int tx = tid & 15, ty = tid >> 4;
    float acc[4][4] = {};
#pragma unroll
    for (int k = 0; k < 16; k++) {
        float a[4], b[4];
#pragma unroll
        for (int ii = 0; ii < 4; ii++) a[ii] = zi[ty * 4 + ii][k];
#pragma unroll
        for (int jj = 0; jj < 4; jj++) b[jj] = zj[tx * 4 + jj][k];
#pragma unroll
        for (int ii = 0; ii < 4; ii++)
#pragma unroll
            for (int jj = 0; jj < 4; jj++) acc[ii][jj] = fmaf(a[ii], b[jj], acc[ii][jj]);
    }
#pragma unroll
    for (int ii = 0; ii < 4; ii++) {
        float4 v;
        v.x = fast_sigmoid(acc[ii][0]);
        v.y = fast_sigmoid(acc[ii][1]);
        v.z = fast_sigmoid(acc[ii][2]);
        v.w = fast_sigmoid(acc[ii][3]);
        *reinterpret_cast<float4*>(&ab[(size_t)(i0 + ty * 4 + ii) * NNODES + j0 + tx * 4]) = v;
    }
}

// =================================================================================
extern "C" void kernel_launch(void* const* d_in, const int* in_sizes, int n_in,
                              void* d_out, int out_size) {
    (void)in_sizes; (void)n_in; (void)out_size;
    const float* x       = (const float*)d_in[0];
    const int*   ei      = (const int*)d_in[1];
    const float* e_noise = (const float*)d_in[2];
    const float* eps     = (const float*)d_in[3];
    const float* W1      = (const float*)d_in[4];
    const float* b1      = (const float*)d_in[5];
    const float* We      = (const float*)d_in[6];
    const float* be      = (const float*)d_in[7];
    const float* Wmu     = (const float*)d_in[8];
    const float* bmu     = (const float*)d_in[9];
    const float* Wsig    = (const float*)d_in[10];
    const float* bsig    = (const float*)d_in[11];
    const float* rk_lgt  = (const float*)d_in[12];
    float* out = (float*)d_out;

    // graph setup
    detect_kernel<<<1, 32>>>(ei);
    zero_kernel<<<16, 256>>>();
    deg_count_kernel<<<NEDGES / 256, 256>>>(ei);
    dinv_kernel<<<16, 256>>>();
    scan_kernel<<<1, 1024>>>();
    csr_fill_kernel<<<NEDGES / 256, 256>>>(ei);

    // feature GEMMs (scratch via symbols INSIDE the kernels)
    sgemm128<0><<<dim3(HID / 128, NNODES / 128), 256>>>(x, W1, IN_CH, 1.0f);
    sgemm128<1><<<dim3(HID / 128, NB_E * NNODES / 128), 256>>>(e_noise, We, E_CH, REWEIGHT);

    // 256-channel propagations
    prop256_kernel<0><<<dim3(NNODES, 1), 256>>>(b1);
    prop256_kernel<1><<<dim3(NNODES, NB_E), 256>>>(be);

    // SNR reductions
    sumsq_kernel<<<dim3(128, 6), 256>>>();

    // mu/sigma: project to 32 channels, propagate 32 channels
    proj_kernel<<<NB_E * NNODES / 8, 256>>>(Wmu, Wsig);
    prop32_kernel<<<NB_E * NNODES * 32 / 256, 256>>>(bmu, bsig, out);

    // z / eps / rk / snr
    z_kernel<<<(NB_Z * NNODES * OUTD + 255) / 256, 256>>>(eps, out);
    finalize_kernel<<<1, 32>>>(rk_lgt, out);

    // decoder
    adj_kernel<<<dim3(NNODES / 64, NNODES / 64, NB_Z), 256>>>(out);
}

// round 6
// speedup vs baseline: 1.0594x; 1.0577x over previous
#include <cuda_runtime.h>
#include <cuda_bf16.h>
#include <cstdint>

#define NNODES 4096
#define NEDGES 131072
#define IN_CH 512
#define E_CH 64
#define HID 256
#define OUTD 16
#define NB_E 5
#define NB_Z 3
#define REWEIGHT 0.6454972243679028f

typedef unsigned long long u64;

__device__ int   g_idx64;
__device__ int   g_deg[NNODES];
__device__ int   g_rowptr[NNODES + 1];
__device__ int   g_cursor[NNODES];
__device__ float g_dinv[NNODES];
__device__ int   g_col[NEDGES];
__device__ float g_w[NEDGES];
__device__ float g_h1[NNODES * HID];
__device__ float g_hx[NNODES * HID];
__device__ __nv_bfloat16 g_he16[NB_E * NNODES * HID];
__device__ float g_we32[E_CH * 32];
__device__ float g_bewc[32];
__device__ float g_the[NB_E * NNODES * 32];
__device__ float g_thx[NNODES * 32];
__device__ float g_t[NB_E * NNODES * 32];
__device__ float g_acc[8];

#define OFF_ADJ 0ull
#define OFF_MU  (OFF_ADJ + 3ull * NNODES * NNODES)
#define OFF_SIG (OFF_MU  + (u64)NB_E * NNODES * OUTD)
#define OFF_Z   (OFF_SIG + (u64)NB_E * NNODES * OUTD)
#define OFF_ZS  (OFF_Z   + (u64)NB_Z * NNODES * OUTD)
#define OFF_EPS (OFF_ZS  + (u64)NB_Z * NNODES * OUTD)
#define OFF_RK  (OFF_EPS + (u64)NB_Z * NNODES * OUTD)
#define OFF_SNR (OFF_RK + 16ull)

// ---------- f32x2 helpers ----------
__device__ __forceinline__ u64 pack2(float a, float b) {
    u64 r; asm("mov.b64 %0, {%1, %2};" : "=l"(r) : "r"(__float_as_int(a)), "r"(__float_as_int(b))); return r;
}
__device__ __forceinline__ void unpack2i(u64 v, int& a, int& b) {
    asm("mov.b64 {%0, %1}, %2;" : "=r"(a), "=r"(b) : "l"(v));
}
__device__ __forceinline__ u64 fma2(u64 a, u64 b, u64 c) {
    u64 d; asm("fma.rn.f32x2 %0, %1, %2, %3;" : "=l"(d) : "l"(a), "l"(b), "l"(c)); return d;
}
__device__ __forceinline__ u64 add2(u64 a, u64 b) {
    u64 d; asm("add.rn.f32x2 %0, %1, %2;" : "=l"(d) : "l"(a), "l"(b)); return d;
}
__device__ __forceinline__ u64 mul2(u64 a, u64 b) {
    u64 d; asm("mul.rn.f32x2 %0, %1, %2;" : "=l"(d) : "l"(a), "l"(b)); return d;
}

// ---------- graph setup ----------
__device__ __forceinline__ int edge_src(const int* ei, int i, int w64) { return w64 ? ei[2 * i] : ei[i]; }
__device__ __forceinline__ int edge_dst(const int* ei, int i, int w64) { return w64 ? ei[2 * (NEDGES + i)] : ei[NEDGES + i]; }

__global__ void detect_kernel(const int* __restrict__ ei) {
    if (threadIdx.x == 0) {
        int nz = 0;
        for (int k = 1; k < 128; k += 2) nz += (ei[k] != 0);
        g_idx64 = (nz == 0) ? 1 : 0;
    }
}
__global__ void zero_kernel() {
    int i = blockIdx.x * blockDim.x + threadIdx.x;
    if (i < NNODES) g_deg[i] = 0;
    if (i < 8) g_acc[i] = 0.0f;
}
__global__ void deg_count_kernel(const int* __restrict__ ei) {
    int i = blockIdx.x * blockDim.x + threadIdx.x;
    int w64 = g_idx64;
    if (i < NEDGES) atomicAdd(&g_deg[edge_dst(ei, i, w64)], 1);
}
__global__ void dinv_kernel() {
    int i = blockIdx.x * blockDim.x + threadIdx.x;
    if (i < NNODES) g_dinv[i] = rsqrtf((float)g_deg[i] + 1.0f);
}
__global__ void scan_kernel() {
    __shared__ int sums[32];
    int tid = threadIdx.x, base = tid * 4;
    int v[4], s = 0;
#pragma unroll
    for (int i = 0; i < 4; i++) { v[i] = g_deg[base + i]; s += v[i]; }
    int lane = tid & 31, wid = tid >> 5, ss = s;
#pragma unroll
    for (int o = 1; o < 32; o <<= 1) { int t = __shfl_up_sync(~0u, ss, o); if (lane >= o) ss += t; }
    if (lane == 31) sums[wid] = ss;
    __syncthreads();
    if (wid == 0) {
        int w = sums[lane];
#pragma unroll
        for (int o = 1; o < 32; o <<= 1) { int t = __shfl_up_sync(~0u, w, o); if (lane >= o) w += t; }
        sums[lane] = w;
    }
    __syncthreads();
    int run = ss - s + (wid > 0 ? sums[wid - 1] : 0);
#pragma unroll
    for (int i = 0; i < 4; i++) { g_rowptr[base + i] = run; g_cursor[base + i] = run; run += v[i]; }
    if (tid == 1023) g_rowptr[NNODES] = run;
}
__global__ void csr_fill_kernel(const int* __restrict__ ei) {
    int i = blockIdx.x * blockDim.x + threadIdx.x;
    if (i >= NEDGES) return;
    int w64 = g_idx64;
    int s = edge_src(ei, i, w64), d = edge_dst(ei, i, w64);
    int pos = atomicAdd(&g_cursor[d], 1);
    g_col[pos] = s;
    g_w[pos] = g_dinv[s] * g_dinv[d];
}

// ---------- SGEMM 64x128, f32x2; DST=0: g_h1 f32, DST=1: g_he16 bf16 ----------
template <int DST>
__global__ __launch_bounds__(256) void sgemm64(const float* __restrict__ A,
                                               const float* __restrict__ B,
                                               int K, float scale) {
    __shared__ float As[8][64];
    __shared__ float Bs[8][128];
    int tid = threadIdx.x;
    const float* Ab = A + (size_t)blockIdx.y * 64 * K;
    const float* Bb = B + blockIdx.x * 128;
    int aRow = tid >> 1, aCol = (tid & 1) * 4;
    int bRow = tid >> 5, bCol = (tid & 31) * 4;
    int ty = tid >> 4, tx = tid & 15;
    u64 acc2[4][4] = {};
    for (int k0 = 0; k0 < K; k0 += 8) {
        float4 a4;
        if (tid < 128) a4 = *reinterpret_cast<const float4*>(Ab + (size_t)aRow * K + k0 + aCol);
        float4 b4 = *reinterpret_cast<const float4*>(Bb + (size_t)(k0 + bRow) * HID + bCol);
        __syncthreads();
        if (tid < 128) {
            As[aCol + 0][aRow] = a4.x; As[aCol + 1][aRow] = a4.y;
            As[aCol + 2][aRow] = a4.z; As[aCol + 3][aRow] = a4.w;
        }
        *reinterpret_cast<float4*>(&Bs[bRow][bCol]) = b4;
        __syncthreads();
#pragma unroll
        for (int kk = 0; kk < 8; kk++) {
            u64 b2[4];
#pragma unroll
            for (int p = 0; p < 4; p++) b2[p] = reinterpret_cast<const u64*>(&Bs[kk][tx * 8])[p];
#pragma unroll
            for (int i = 0; i < 4; i++) {
                float a = As[kk][ty * 4 + i];
                u64 a2 = pack2(a, a);
#pragma unroll
                for (int p = 0; p < 4; p++) acc2[i][p] = fma2(a2, b2[p], acc2[i][p]);
            }
        }
    }
#pragma unroll
    for (int i = 0; i < 4; i++) {
        size_t row = (size_t)blockIdx.y * 64 + ty * 4 + i;
        int col = blockIdx.x * 128 + tx * 8;
        float v[8];
#pragma unroll
        for (int p = 0; p < 4; p++) {
            int lo, hi; unpack2i(acc2[i][p], lo, hi);
            v[2 * p] = __int_as_float(lo) * scale; v[2 * p + 1] = __int_as_float(hi) * scale;
        }
        if (DST == 0) {
            float4 o0 = {v[0], v[1], v[2], v[3]}, o1 = {v[4], v[5], v[6], v[7]};
            *reinterpret_cast<float4*>(&g_h1[row * HID + col]) = o0;
            *reinterpret_cast<float4*>(&g_h1[row * HID + col + 4]) = o1;
        } else {
            __nv_bfloat162 h[4];
#pragma unroll
            for (int p = 0; p < 4; p++) h[p] = __floats2bfloat162_rn(v[2 * p], v[2 * p + 1]);
            *reinterpret_cast<uint4*>(&g_he16[row * HID + col]) = *reinterpret_cast<uint4*>(h);
        }
    }
}

// ---------- hx = relu(P(h1)+b1), fused sumsq ----------
__global__ __launch_bounds__(256) void prop256x_kernel(const float* __restrict__ bias) {
    int n = blockIdx.x, c = threadIdx.x;
    int start = g_rowptr[n], end = g_rowptr[n + 1];
    float d = g_dinv[n];
    float acc = g_h1[(size_t)n * HID + c] * d * d;
    for (int j = start; j < end; j++)
        acc = fmaf(g_w[j], g_h1[(size_t)g_col[j] * HID + c], acc);
    acc = fmaxf(acc + bias[c], 0.0f);
    g_hx[(size_t)n * HID + c] = acc;
    float s = acc * acc;
#pragma unroll
    for (int o = 16; o > 0; o >>= 1) s += __shfl_down_sync(~0u, s, o);
    __shared__ float ws[8];
    if ((c & 31) == 0) ws[c >> 5] = s;
    __syncthreads();
    if (c < 8) {
        s = ws[c];
#pragma unroll
        for (int o = 4; o > 0; o >>= 1) s += __shfl_down_sync(0xffu, s, o);
        if (c == 0) atomicAdd(&g_acc[0], s);
    }
}

// ---------- sumsq(P(he)+be) per batch, bf16 gathers, no store ----------
__global__ __launch_bounds__(128) void prop256e_kernel(const float* __restrict__ be) {
    int n = blockIdx.x, b = blockIdx.y, c2 = threadIdx.x;
    const __nv_bfloat162* hb =
        reinterpret_cast<const __nv_bfloat162*>(g_he16 + (size_t)b * NNODES * HID);
    int start = g_rowptr[n], end = g_rowptr[n + 1];
    float d = g_dinv[n];
    float2 self = __bfloat1622float2(hb[n * 128 + c2]);
    float ax = self.x * d * d, ay = self.y * d * d;
    for (int j = start; j < end; j++) {
        float w = g_w[j];
        float2 v = __bfloat1622float2(hb[g_col[j] * 128 + c2]);
        ax = fmaf(w, v.x, ax); ay = fmaf(w, v.y, ay);
    }
    ax += be[2 * c2]; ay += be[2 * c2 + 1];
    float s = ax * ax + ay * ay;
#pragma unroll
    for (int o = 16; o > 0; o >>= 1) s += __shfl_down_sync(~0u, s, o);
    __shared__ float ws[4];
    if ((c2 & 31) == 0) ws[c2 >> 5] = s;
    __syncthreads();
    if (c2 == 0) atomicAdd(&g_acc[1 + b], ws[0] + ws[1] + ws[2] + ws[3]);
}

// ---------- small projections ----------
__global__ void we32_kernel(const float* __restrict__ We, const float* __restrict__ Wmu,
                            const float* __restrict__ Wsig) {
    int idx = blockIdx.x * 256 + threadIdx.x;   // 2048
    int i = idx >> 5, j = idx & 31;
    const float* W = (j < 16) ? Wmu : Wsig;
    int jj = j & 15;
    float acc = 0.0f;
#pragma unroll 8
    for (int k = 0; k < HID; k++) acc = fmaf(We[i * HID + k], W[k * 16 + jj], acc);
    g_we32[i * 32 + j] = acc;
}
__global__ void bewc_kernel(const float* __restrict__ be, const float* __restrict__ Wmu,
                            const float* __restrict__ Wsig) {
    int j = threadIdx.x;
    const float* W = (j < 16) ? Wmu : Wsig;
    int jj = j & 15;
    float acc = 0.0f;
    for (int k = 0; k < HID; k++) acc = fmaf(be[k], W[k * 16 + jj], acc);
    g_bewc[j] = acc;
}
// the = REWEIGHT * e_noise @ we32  (8 rows/block)
__global__ __launch_bounds__(256) void the_kernel(const float* __restrict__ e_noise) {
    __shared__ float se[8][64];
    __shared__ float sw[64 * 32];
    int r0 = blockIdx.x * 8, tid = threadIdx.x;
    for (int i = tid; i < 512; i += 256)
        se[i >> 6][i & 63] = e_noise[(size_t)(r0 + (i >> 6)) * 64 + (i & 63)] * REWEIGHT;
    for (int i = tid; i < 2048; i += 256) sw[i] = g_we32[i];
    __syncthreads();
    int lr = tid >> 5, c = tid & 31;
    float acc = 0.0f;
#pragma unroll 8
    for (int k = 0; k < 64; k++) acc = fmaf(se[lr][k], sw[k * 32 + c], acc);
    g_the[(size_t)(r0 + lr) * 32 + c] = acc;
}
// thx = hx @ [Wmu|Wsig]  (8 rows/block)
__global__ __launch_bounds__(256) void thx_kernel(const float* __restrict__ Wmu,
                                                  const float* __restrict__ Wsig) {
    __shared__ float s[8 * 256];
    int r0 = blockIdx.x * 8, tid = threadIdx.x;
    for (int i = tid; i < 2048; i += 256)
        s[i] = g_hx[(size_t)r0 * HID + i];
    __syncthreads();
    int lr = tid >> 5, c = tid & 31;
    const float* W = (c < 16) ? Wmu : Wsig;
    int cc = c & 15;
    float acc = 0.0f;
    const float* srow = &s[lr * 256];
#pragma unroll 8
    for (int k = 0; k < 256; k++) acc = fmaf(srow[k], W[k * 16 + cc], acc);
    g_thx[(size_t)(r0 + lr) * 32 + c] = acc;
}
// t = thx + P(the) + bewc
__global__ void tmid_kernel() {
    int warp = (blockIdx.x * blockDim.x + threadIdx.x) >> 5;
    int lane = threadIdx.x & 31;
    int b = warp >> 12, n = warp & (NNODES - 1);
    const float* tb = g_the + (size_t)b * NNODES * 32;
    float d = g_dinv[n];
    float acc = tb[(size_t)n * 32 + lane] * d * d;
    int start = g_rowptr[n], end = g_rowptr[n + 1];
    for (int j = start; j < end; j++)
        acc = fmaf(g_w[j], tb[(size_t)g_col[j] * 32 + lane], acc);
    g_t[(size_t)warp * 32 + lane] = acc + g_thx[(size_t)n * 32 + lane] + g_bewc[lane];
}
// mu/sig = P(t) + bias
__global__ void prop32_kernel(const float* __restrict__ bmu, const float* __restrict__ bsig,
                              float* __restrict__ out) {
    int warp = (blockIdx.x * blockDim.x + threadIdx.x) >> 5;
    int lane = threadIdx.x & 31;
    int b = warp >> 12, n = warp & (NNODES - 1);
    const float* tb = g_t + (size_t)b * NNODES * 32;
    float d = g_dinv[n];
    float acc = tb[(size_t)n * 32 + lane] * d * d;
    int start = g_rowptr[n], end = g_rowptr[n + 1];
    for (int j = start; j < end; j++)
        acc = fmaf(g_w[j], tb[(size_t)g_col[j] * 32 + lane], acc);
    size_t base = ((size_t)b * NNODES + n) * OUTD;
    if (lane < 16) out[OFF_MU + base + lane] = acc + bmu[lane];
    else           out[OFF_SIG + base + (lane - 16)] = acc + bsig[lane - 16];
}

__global__ void z_kernel(const float* __restrict__ eps, float* __restrict__ out) {
    int i = blockIdx.x * blockDim.x + threadIdx.x;
    if (i >= NB_Z * NNODES * OUTD) return;
    int b = i / (NNODES * OUTD);
    int rem = i - b * (NNODES * OUTD);
    size_t src = (size_t)(b + 2) * NNODES * OUTD + rem;
    float zv = fmaf(eps[i], expf(0.5f * out[OFF_SIG + src]), out[OFF_MU + src]);
    out[OFF_Z + i] = zv;
    out[OFF_ZS + i] = zv;
    out[OFF_EPS + i] = eps[i];
}
__global__ void finalize_kernel(const float* __restrict__ rk_lgt, float* __restrict__ out) {
    int t = threadIdx.x;
    if (t < 5) out[OFF_SNR + t] = g_acc[0] / g_acc[1 + t];
    if (t < 16) out[OFF_RK + t] = sqrtf(1.0f / (1.0f + expf(-rk_lgt[t])));
}

// ---------- packed FMA-only sigmoid ----------
__device__ __forceinline__ u64 sigmoid2(u64 x2) {
    const float MG = 12582912.0f;
    u64 t2 = mul2(x2, pack2(-1.4426950408889634f, -1.4426950408889634f));
    u64 z2 = add2(t2, pack2(MG, MG));
    int n0, n1; unpack2i(z2, n0, n1);
    u64 zm2 = add2(z2, pack2(-MG, -MG));
    u64 f2 = fma2(zm2, pack2(-1.0f, -1.0f), t2);
    u64 p2 = pack2(1.3333558146e-3f, 1.3333558146e-3f);
    p2 = fma2(p2, f2, pack2(9.6181291076e-3f, 9.6181291076e-3f));
    p2 = fma2(p2, f2, pack2(5.5504108665e-2f, 5.5504108665e-2f));
    p2 = fma2(p2, f2, pack2(2.4022650696e-1f, 2.4022650696e-1f));
    p2 = fma2(p2, f2, pack2(6.9314718056e-1f, 6.9314718056e-1f));
    p2 = fma2(p2, f2, pack2(1.0f, 1.0f));
    int i0, i1; unpack2i(p2, i0, i1);
    u64 u2 = pack2(__int_as_float(i0 + (n0 << 23)), __int_as_float(i1 + (n1 << 23)));
    u64 d2 = add2(u2, pack2(1.0f, 1.0f));
    int di0, di1; unpack2i(d2, di0, di1);
    u64 r2 = pack2(__int_as_float(0x7EF311C3 - di0), __int_as_float(0x7EF311C3 - di1));
    u64 nd2 = mul2(d2, pack2(-1.0f, -1.0f));
    const u64 two2 = pack2(2.0f, 2.0f);
    r2 = mul2(r2, fma2(nd2, r2, two2));
    r2 = mul2(r2, fma2(nd2, r2, two2));
    r2 = mul2(r2, fma2(nd2, r2, two2));
    return r2;
}

// ---------- adj = sigmoid(z @ z^T), 64x64 tile, f32x2 ----------
__global__ __launch_bounds__(256) void adj_kernel(float* __restrict__ out) {
    const float* zb = out + OFF_Z + (size_t)blockIdx.z * NNODES * OUTD;
    float* ab = out + OFF_ADJ + (size_t)blockIdx.z * NNODES * NNODES;
    __shared__ float zi[64][17];
    __shared__ float zjT[16][64];
    int i0 = blockIdx.y * 64, j0 = blockIdx.x * 64;
    int tid = threadIdx.x;
    for (int t = tid; t < 1024; t += 256) {
        int r = t >> 4, k = t & 15;
        zi[r][k] = zb[(size_t)(i0 + r) * 16 + k];
        int k2 = t >> 6, r2 = t & 63;
        zjT[k2][r2] = zb[(size_t)(j0 + r2) * 16 + k2];
    }
    __syncthreads();
    int tx = tid & 15, ty = tid >> 4;
    u64 acc2[4][2] = {};
#pragma unroll
    for (int k = 0; k < 16; k++) {
        u64 b0 = *reinterpret_cast<const u64*>(&zjT[k][tx * 4]);
        u64 b1 = *reinterpret_cast<const u64*>(&zjT[k][tx * 4 + 2]);
#pragma unroll
        for (int i = 0; i < 4; i++) {
            float a = zi[ty * 4 + i][k];
            u64 a2 = pack2(a, a);
            acc2[i][0] = fma2(a2, b0, acc2[i][0]);
            acc2[i][1] = fma2(a2, b1, acc2[i][1]);
        }
    }
#pragma unroll
    for (int i = 0; i < 4; i++) {
        u64 s0 = sigmoid2(acc2[i][0]);
        u64 s1 = sigmoid2(acc2[i][1]);
        int a0, a1, b0, b1;
        unpack2i(s0, a0, a1); unpack2i(s1, b0, b1);
        float4 v = {__int_as_float(a0), __int_as_float(a1), __int_as_float(b0), __int_as_float(b1)};
        *reinterpret_cast<float4*>(&ab[(size_t)(i0 + ty * 4 + i) * NNODES + j0 + tx * 4]) = v;
    }
}

// =================================================================================
extern "C" void kernel_launch(void* const* d_in, const int* in_sizes, int n_in,
                              void* d_out, int out_size) {
    (void)in_sizes; (void)n_in; (void)out_size;
    const float* x       = (const float*)d_in[0];
    const int*   ei      = (const int*)d_in[1];
    const float* e_noise = (const float*)d_in[2];
    const float* eps     = (const float*)d_in[3];
    const float* W1      = (const float*)d_in[4];
    const float* b1      = (const float*)d_in[5];
    const float* We      = (const float*)d_in[6];
    const float* be      = (const float*)d_in[7];
    const float* Wmu     = (const float*)d_in[8];
    const float* bmu     = (const float*)d_in[9];
    const float* Wsig    = (const float*)d_in[10];
    const float* bsig    = (const float*)d_in[11];
    const float* rk_lgt  = (const float*)d_in[12];
    float* out = (float*)d_out;

    detect_kernel<<<1, 32>>>(ei);
    zero_kernel<<<16, 256>>>();
    deg_count_kernel<<<NEDGES / 256, 256>>>(ei);
    dinv_kernel<<<16, 256>>>();
    scan_kernel<<<1, 1024>>>();
    csr_fill_kernel<<<NEDGES / 256, 256>>>(ei);

    sgemm64<0><<<dim3(2, NNODES / 64), 256>>>(x, W1, IN_CH, 1.0f);
    sgemm64<1><<<dim3(2, NB_E * NNODES / 64), 256>>>(e_noise, We, E_CH, REWEIGHT);

    prop256x_kernel<<<NNODES, 256>>>(b1);
    prop256e_kernel<<<dim3(NNODES, NB_E), 128>>>(be);

    we32_kernel<<<8, 256>>>(We, Wmu, Wsig);
    bewc_kernel<<<1, 32>>>(be, Wmu, Wsig);
    the_kernel<<<NB_E * NNODES / 8, 256>>>(e_noise);
    thx_kernel<<<NNODES / 8, 256>>>(Wmu, Wsig);
    tmid_kernel<<<NB_E * NNODES / 8, 256>>>();
    prop32_kernel<<<NB_E * NNODES / 8, 256>>>(bmu, bsig, out);

    z_kernel<<<(NB_Z * NNODES * OUTD + 255) / 256, 256>>>(eps, out);
    finalize_kernel<<<1, 32>>>(rk_lgt, out);

    adj_kernel<<<dim3(NNODES / 64, NNODES / 64, NB_Z), 256>>>(out);
}

// round 7
// speedup vs baseline: 1.2902x; 1.2179x over previous
#include <cuda_runtime.h>
#include <cuda_bf16.h>
#include <cstdint>

#define NNODES 4096
#define NEDGES 131072
#define IN_CH 512
#define E_CH 64
#define HID 256
#define OUTD 16
#define NB_E 5
#define NB_Z 3
#define REWEIGHT 0.6454972243679028f

typedef unsigned long long u64;

__device__ int   g_idx64;
__device__ int   g_deg[NNODES];
__device__ int   g_rowptr[NNODES + 1];
__device__ int   g_cursor[NNODES];
__device__ float g_dinv[NNODES];
__device__ int   g_col[NEDGES];
__device__ float g_w[NEDGES];
__device__ float g_h1[NNODES * HID];
__device__ float g_hx[NNODES * HID];
__device__ __nv_bfloat16 g_he16[NB_E * NNODES * HID];
__device__ float g_we32[E_CH * 32];
__device__ float g_bewc[32];
__device__ float g_the[NB_E * NNODES * 32];
__device__ float g_thx[NNODES * 32];
__device__ float g_t[NB_E * NNODES * 32];
__device__ float g_acc[8];

#define OFF_ADJ 0ull
#define OFF_MU  (OFF_ADJ + 3ull * NNODES * NNODES)
#define OFF_SIG (OFF_MU  + (u64)NB_E * NNODES * OUTD)
#define OFF_Z   (OFF_SIG + (u64)NB_E * NNODES * OUTD)
#define OFF_ZS  (OFF_Z   + (u64)NB_Z * NNODES * OUTD)
#define OFF_EPS (OFF_ZS  + (u64)NB_Z * NNODES * OUTD)
#define OFF_RK  (OFF_EPS + (u64)NB_Z * NNODES * OUTD)
#define OFF_SNR (OFF_RK + 16ull)

// ---------- f32x2 helpers ----------
__device__ __forceinline__ u64 pack2(float a, float b) {
    u64 r; asm("mov.b64 %0, {%1, %2};" : "=l"(r) : "r"(__float_as_int(a)), "r"(__float_as_int(b))); return r;
}
__device__ __forceinline__ void unpack2f(u64 v, float& a, float& b) {
    int x, y; asm("mov.b64 {%0, %1}, %2;" : "=r"(x), "=r"(y) : "l"(v));
    a = __int_as_float(x); b = __int_as_float(y);
}
__device__ __forceinline__ u64 fma2(u64 a, u64 b, u64 c) {
    u64 d; asm("fma.rn.f32x2 %0, %1, %2, %3;" : "=l"(d) : "l"(a), "l"(b), "l"(c)); return d;
}

// ---------- graph setup ----------
__device__ __forceinline__ int edge_src(const int* ei, int i, int w64) { return w64 ? ei[2 * i] : ei[i]; }
__device__ __forceinline__ int edge_dst(const int* ei, int i, int w64) { return w64 ? ei[2 * (NEDGES + i)] : ei[NEDGES + i]; }

__global__ void setup_kernel(const int* __restrict__ ei) {
    int i = blockIdx.x * blockDim.x + threadIdx.x;
    if (i < NNODES) g_deg[i] = 0;
    if (i < 8) g_acc[i] = 0.0f;
    if (blockIdx.x == 0 && threadIdx.x == 0) {
        int nz = 0;
        for (int k = 1; k < 128; k += 2) nz += (ei[k] != 0);
        g_idx64 = (nz == 0) ? 1 : 0;
    }
}
__global__ void deg_count_kernel(const int* __restrict__ ei) {
    int i = blockIdx.x * blockDim.x + threadIdx.x;
    int w64 = g_idx64;
    if (i < NEDGES) atomicAdd(&g_deg[edge_dst(ei, i, w64)], 1);
}
// dinv + exclusive scan, one block of 1024
__global__ void dinv_scan_kernel() {
    __shared__ int sums[32];
    int tid = threadIdx.x, base = tid * 4;
    int v[4], s = 0;
#pragma unroll
    for (int i = 0; i < 4; i++) {
        v[i] = g_deg[base + i];
        g_dinv[base + i] = rsqrtf((float)v[i] + 1.0f);
        s += v[i];
    }
    int lane = tid & 31, wid = tid >> 5, ss = s;
#pragma unroll
    for (int o = 1; o < 32; o <<= 1) { int t = __shfl_up_sync(~0u, ss, o); if (lane >= o) ss += t; }
    if (lane == 31) sums[wid] = ss;
    __syncthreads();
    if (wid == 0) {
        int w = sums[lane];
#pragma unroll
        for (int o = 1; o < 32; o <<= 1) { int t = __shfl_up_sync(~0u, w, o); if (lane >= o) w += t; }
        sums[lane] = w;
    }
    __syncthreads();
    int run = ss - s + (wid > 0 ? sums[wid - 1] : 0);
#pragma unroll
    for (int i = 0; i < 4; i++) { g_rowptr[base + i] = run; g_cursor[base + i] = run; run += v[i]; }
    if (tid == 1023) g_rowptr[NNODES] = run;
}
__global__ void csr_fill_kernel(const int* __restrict__ ei) {
    int i = blockIdx.x * blockDim.x + threadIdx.x;
    if (i >= NEDGES) return;
    int w64 = g_idx64;
    int s = edge_src(ei, i, w64), d = edge_dst(ei, i, w64);
    int pos = atomicAdd(&g_cursor[d], 1);
    g_col[pos] = s;
    g_w[pos] = g_dinv[s] * g_dinv[d];
}

// ---------- SGEMM 64x128, BK=16, f32x2; DST=0: g_h1 f32, DST=1: g_he16 bf16 ----
template <int DST>
__global__ __launch_bounds__(256) void sgemm16(const float* __restrict__ A,
                                               const float* __restrict__ B,
                                               int K, float scale) {
    __shared__ float As[16][65];
    __shared__ float Bs[16][128];
    int tid = threadIdx.x;
    const float* Ab = A + (size_t)blockIdx.y * 64 * K;
    const float* Bb = B + blockIdx.x * 128;
    int aRow = tid >> 2, aCol = (tid & 3) * 4;
    int bRow = tid >> 5, bCol = (tid & 31) * 4;
    int ty = tid >> 4, tx = tid & 15;
    u64 acc2[4][4] = {};
    for (int k0 = 0; k0 < K; k0 += 16) {
        float4 a4 = *reinterpret_cast<const float4*>(Ab + (size_t)aRow * K + k0 + aCol);
        float4 b4a = *reinterpret_cast<const float4*>(Bb + (size_t)(k0 + bRow) * HID + bCol);
        float4 b4b = *reinterpret_cast<const float4*>(Bb + (size_t)(k0 + bRow + 8) * HID + bCol);
        __syncthreads();
        As[aCol + 0][aRow] = a4.x; As[aCol + 1][aRow] = a4.y;
        As[aCol + 2][aRow] = a4.z; As[aCol + 3][aRow] = a4.w;
        *reinterpret_cast<float4*>(&Bs[bRow][bCol]) = b4a;
        *reinterpret_cast<float4*>(&Bs[bRow + 8][bCol]) = b4b;
        __syncthreads();
#pragma unroll
        for (int kk = 0; kk < 16; kk++) {
            u64 b2[4];
#pragma unroll
            for (int p = 0; p < 4; p++) b2[p] = reinterpret_cast<const u64*>(&Bs[kk][tx * 8])[p];
#pragma unroll
            for (int i = 0; i < 4; i++) {
                float a = As[kk][ty * 4 + i];
                u64 a2 = pack2(a, a);
#pragma unroll
                for (int p = 0; p < 4; p++) acc2[i][p] = fma2(a2, b2[p], acc2[i][p]);
            }
        }
    }
#pragma unroll
    for (int i = 0; i < 4; i++) {
        size_t row = (size_t)blockIdx.y * 64 + ty * 4 + i;
        int col = blockIdx.x * 128 + tx * 8;
        float v[8];
#pragma unroll
        for (int p = 0; p < 4; p++) {
            float lo, hi; unpack2f(acc2[i][p], lo, hi);
            v[2 * p] = lo * scale; v[2 * p + 1] = hi * scale;
        }
        if (DST == 0) {
            float4 o0 = {v[0], v[1], v[2], v[3]}, o1 = {v[4], v[5], v[6], v[7]};
            *reinterpret_cast<float4*>(&g_h1[row * HID + col]) = o0;
            *reinterpret_cast<float4*>(&g_h1[row * HID + col + 4]) = o1;
        } else {
            __nv_bfloat162 h[4];
#pragma unroll
            for (int p = 0; p < 4; p++) h[p] = __floats2bfloat162_rn(v[2 * p], v[2 * p + 1]);
            *reinterpret_cast<uint4*>(&g_he16[row * HID + col]) = *reinterpret_cast<uint4*>(h);
        }
    }
}

// ---------- hx = relu(P(h1)+b1), fused sumsq ----------
__global__ __launch_bounds__(256) void prop256x_kernel(const float* __restrict__ bias) {
    int n = blockIdx.x, c = threadIdx.x;
    int start = g_rowptr[n], end = g_rowptr[n + 1];
    float d = g_dinv[n];
    float acc = g_h1[(size_t)n * HID + c] * d * d;
    for (int j = start; j < end; j++)
        acc = fmaf(g_w[j], g_h1[(size_t)g_col[j] * HID + c], acc);
    acc = fmaxf(acc + bias[c], 0.0f);
    g_hx[(size_t)n * HID + c] = acc;
    float s = acc * acc;
#pragma unroll
    for (int o = 16; o > 0; o >>= 1) s += __shfl_down_sync(~0u, s, o);
    __shared__ float ws[8];
    if ((c & 31) == 0) ws[c >> 5] = s;
    __syncthreads();
    if (c < 8) {
        s = ws[c];
#pragma unroll
        for (int o = 4; o > 0; o >>= 1) s += __shfl_down_sync(0xffu, s, o);
        if (c == 0) atomicAdd(&g_acc[0], s);
    }
}

// ---------- sumsq(P(he)+be) per batch, bf16 gathers, no store ----------
__global__ __launch_bounds__(128) void prop256e_kernel(const float* __restrict__ be) {
    int n = blockIdx.x, b = blockIdx.y, c2 = threadIdx.x;
    const __nv_bfloat162* hb =
        reinterpret_cast<const __nv_bfloat162*>(g_he16 + (size_t)b * NNODES * HID);
    int start = g_rowptr[n], end = g_rowptr[n + 1];
    float d = g_dinv[n];
    float2 self = __bfloat1622float2(hb[n * 128 + c2]);
    float ax = self.x * d * d, ay = self.y * d * d;
    for (int j = start; j < end; j++) {
        float w = g_w[j];
        float2 v = __bfloat1622float2(hb[g_col[j] * 128 + c2]);
        ax = fmaf(w, v.x, ax); ay = fmaf(w, v.y, ay);
    }
    ax += be[2 * c2]; ay += be[2 * c2 + 1];
    float s = ax * ax + ay * ay;
#pragma unroll
    for (int o = 16; o > 0; o >>= 1) s += __shfl_down_sync(~0u, s, o);
    __shared__ float ws[4];
    if ((c2 & 31) == 0) ws[c2 >> 5] = s;
    __syncthreads();
    if (c2 == 0) atomicAdd(&g_acc[1 + b], ws[0] + ws[1] + ws[2] + ws[3]);
}

// ---------- we32 = We@[Wmu|Wsig] (blocks 0-7) + bewc = be@[Wmu|Wsig] (block 8) --
__global__ void wproj_kernel(const float* __restrict__ We, const float* __restrict__ be,
                             const float* __restrict__ Wmu, const float* __restrict__ Wsig) {
    if (blockIdx.x < 8) {
        int idx = blockIdx.x * 256 + threadIdx.x;
        int i = idx >> 5, j = idx & 31;
        const float* W = (j < 16) ? Wmu : Wsig;
        int jj = j & 15;
        float acc = 0.0f;
#pragma unroll 8
        for (int k = 0; k < HID; k++) acc = fmaf(We[i * HID + k], W[k * 16 + jj], acc);
        g_we32[i * 32 + j] = acc;
    } else if (threadIdx.x < 32) {
        int j = threadIdx.x;
        const float* W = (j < 16) ? Wmu : Wsig;
        int jj = j & 15;
        float acc = 0.0f;
        for (int k = 0; k < HID; k++) acc = fmaf(be[k], W[k * 16 + jj], acc);
        g_bewc[j] = acc;
    }
}
// ---------- the = R*e@we32 (blocks<2560) | thx = hx@[Wmu|Wsig] (blocks>=2560) ---
__global__ __launch_bounds__(256) void midproj_kernel(const float* __restrict__ e_noise,
                                                      const float* __restrict__ Wmu,
                                                      const float* __restrict__ Wsig) {
    int tid = threadIdx.x;
    int lr = tid >> 5, c = tid & 31;
    if (blockIdx.x < 2560) {
        __shared__ float se[8][64];
        __shared__ float sw[64 * 32];
        int r0 = blockIdx.x * 8;
        for (int i = tid; i < 512; i += 256)
            se[i >> 6][i & 63] = e_noise[(size_t)(r0 + (i >> 6)) * 64 + (i & 63)] * REWEIGHT;
        for (int i = tid; i < 2048; i += 256) sw[i] = g_we32[i];
        __syncthreads();
        float acc = 0.0f;
#pragma unroll 8
        for (int k = 0; k < 64; k++) acc = fmaf(se[lr][k], sw[k * 32 + c], acc);
        g_the[(size_t)(r0 + lr) * 32 + c] = acc;
    } else {
        __shared__ float s[8 * 256];
        int r0 = (blockIdx.x - 2560) * 8;
        for (int i = tid; i < 2048; i += 256) s[i] = g_hx[(size_t)r0 * HID + i];
        __syncthreads();
        const float* W = (c < 16) ? Wmu : Wsig;
        int cc = c & 15;
        float acc = 0.0f;
        const float* srow = &s[lr * 256];
#pragma unroll 8
        for (int k = 0; k < 256; k++) acc = fmaf(srow[k], W[k * 16 + cc], acc);
        g_thx[(size_t)(r0 + lr) * 32 + c] = acc;
    }
}
// ---------- t = thx + P(the) + bewc ----------
__global__ void tmid_kernel() {
    int warp = (blockIdx.x * blockDim.x + threadIdx.x) >> 5;
    int lane = threadIdx.x & 31;
    int b = warp >> 12, n = warp & (NNODES - 1);
    const float* tb = g_the + (size_t)b * NNODES * 32;
    float d = g_dinv[n];
    float acc = tb[(size_t)n * 32 + lane] * d * d;
    int start = g_rowptr[n], end = g_rowptr[n + 1];
    for (int j = start; j < end; j++)
        acc = fmaf(g_w[j], tb[(size_t)g_col[j] * 32 + lane], acc);
    g_t[(size_t)warp * 32 + lane] = acc + g_thx[(size_t)n * 32 + lane] + g_bewc[lane];
}
// ---------- mu/sig = P(t) + bias ----------
__global__ void prop32_kernel(const float* __restrict__ bmu, const float* __restrict__ bsig,
                              float* __restrict__ out) {
    int warp = (blockIdx.x * blockDim.x + threadIdx.x) >> 5;
    int lane = threadIdx.x & 31;
    int b = warp >> 12, n = warp & (NNODES - 1);
    const float* tb = g_t + (size_t)b * NNODES * 32;
    float d = g_dinv[n];
    float acc = tb[(size_t)n * 32 + lane] * d * d;
    int start = g_rowptr[n], end = g_rowptr[n + 1];
    for (int j = start; j < end; j++)
        acc = fmaf(g_w[j], tb[(size_t)g_col[j] * 32 + lane], acc);
    size_t base = ((size_t)b * NNODES + n) * OUTD;
    if (lane < 16) out[OFF_MU + base + lane] = acc + bmu[lane];
    else           out[OFF_SIG + base + (lane - 16)] = acc + bsig[lane - 16];
}

// ---------- z + finalize ----------
__global__ void zfin_kernel(const float* __restrict__ eps, const float* __restrict__ rk_lgt,
                            float* __restrict__ out) {
    int i = blockIdx.x * blockDim.x + threadIdx.x;
    int b = i / (NNODES * OUTD);
    int rem = i - b * (NNODES * OUTD);
    size_t src = (size_t)(b + 2) * NNODES * OUTD + rem;
    float zv = fmaf(eps[i], __expf(0.5f * out[OFF_SIG + src]), out[OFF_MU + src]);
    out[OFF_Z + i] = zv;
    out[OFF_ZS + i] = zv;
    out[OFF_EPS + i] = eps[i];
    if (blockIdx.x == 0 && threadIdx.x < 32) {
        int t = threadIdx.x;
        if (t < 5) out[OFF_SNR + t] = g_acc[0] / g_acc[1 + t];
        if (t < 16) out[OFF_RK + t] = sqrtf(1.0f / (1.0f + expf(-rk_lgt[t])));
    }
}

// ---------- adj = sigmoid(z z^T): 128x128 tile, MUFU sigmoid ----------
__device__ __forceinline__ float sigmoid1(float x) {
    float e = __expf(-x);
    float d = 1.0f + e;
    float r; asm("rcp.approx.f32 %0, %1;" : "=f"(r) : "f"(d));
    return r;
}

__global__ __launch_bounds__(256) void adj_kernel(float* __restrict__ out) {
    const float* zb = out + OFF_Z + (size_t)blockIdx.z * NNODES * OUTD;
    float* ab = out + OFF_ADJ + (size_t)blockIdx.z * NNODES * NNODES;
    __shared__ float ziT[16][132];
    __shared__ float zjT[16][132];
    int i0 = blockIdx.y * 128, j0 = blockIdx.x * 128;
    int tid = threadIdx.x;
#pragma unroll
    for (int rnd = 0; rnd < 2; rnd++) {
        int L4 = tid + rnd * 256;            // float4 index within 2048 floats
        float4 a = *reinterpret_cast<const float4*>(zb + (size_t)i0 * 16 + L4 * 4);
        float4 b = *reinterpret_cast<const float4*>(zb + (size_t)j0 * 16 + L4 * 4);
        int r = L4 >> 2, k0 = (L4 & 3) * 4;
        ziT[k0 + 0][r] = a.x; ziT[k0 + 1][r] = a.y; ziT[k0 + 2][r] = a.z; ziT[k0 + 3][r] = a.w;
        zjT[k0 + 0][r] = b.x; zjT[k0 + 1][r] = b.y; zjT[k0 + 2][r] = b.z; zjT[k0 + 3][r] = b.w;
    }
    __syncthreads();
    int tx = tid & 15, ty = tid >> 4;
    u64 acc2[8][4] = {};
#pragma unroll
    for (int k = 0; k < 16; k++) {
        float4 b0 = *reinterpret_cast<const float4*>(&zjT[k][tx * 8]);
        float4 b1 = *reinterpret_cast<const float4*>(&zjT[k][tx * 8 + 4]);
        u64 b2[4];
        b2[0] = pack2(b0.x, b0.y); b2[1] = pack2(b0.z, b0.w);
        b2[2] = pack2(b1.x, b1.y); b2[3] = pack2(b1.z, b1.w);
        float4 a0 = *reinterpret_cast<const float4*>(&ziT[k][ty * 8]);
        float4 a1 = *reinterpret_cast<const float4*>(&ziT[k][ty * 8 + 4]);
        float av[8] = {a0.x, a0.y, a0.z, a0.w, a1.x, a1.y, a1.z, a1.w};
#pragma unroll
        for (int i = 0; i < 8; i++) {
            u64 a2 = pack2(av[i], av[i]);
#pragma unroll
            for (int p = 0; p < 4; p++) acc2[i][p] = fma2(a2, b2[p], acc2[i][p]);
        }
    }
#pragma unroll
    for (int i = 0; i < 8; i++) {
        float v[8];
#pragma unroll
        for (int p = 0; p < 4; p++) unpack2f(acc2[i][p], v[2 * p], v[2 * p + 1]);
        float4 o0, o1;
        o0.x = sigmoid1(v[0]); o0.y = sigmoid1(v[1]); o0.z = sigmoid1(v[2]); o0.w = sigmoid1(v[3]);
        o1.x = sigmoid1(v[4]); o1.y = sigmoid1(v[5]); o1.z = sigmoid1(v[6]); o1.w = sigmoid1(v[7]);
        float* row = ab + (size_t)(i0 + ty * 8 + i) * NNODES + j0 + tx * 8;
        *reinterpret_cast<float4*>(row) = o0;
        *reinterpret_cast<float4*>(row + 4) = o1;
    }
}

// =================================================================================
extern "C" void kernel_launch(void* const* d_in, const int* in_sizes, int n_in,
                              void* d_out, int out_size) {
    (void)in_sizes; (void)n_in; (void)out_size;
    const float* x       = (const float*)d_in[0];
    const int*   ei      = (const int*)d_in[1];
    const float* e_noise = (const float*)d_in[2];
    const float* eps     = (const float*)d_in[3];
    const float* W1      = (const float*)d_in[4];
    const float* b1      = (const float*)d_in[5];
    const float* We      = (const float*)d_in[6];
    const float* be      = (const float*)d_in[7];
    const float* Wmu     = (const float*)d_in[8];
    const float* bmu     = (const float*)d_in[9];
    const float* Wsig    = (const float*)d_in[10];
    const float* bsig    = (const float*)d_in[11];
    const float* rk_lgt  = (const float*)d_in[12];
    float* out = (float*)d_out;

    setup_kernel<<<16, 256>>>(ei);
    deg_count_kernel<<<NEDGES / 256, 256>>>(ei);
    dinv_scan_kernel<<<1, 1024>>>();
    csr_fill_kernel<<<NEDGES / 256, 256>>>(ei);

    sgemm16<0><<<dim3(2, NNODES / 64), 256>>>(x, W1, IN_CH, 1.0f);
    sgemm16<1><<<dim3(2, NB_E * NNODES / 64), 256>>>(e_noise, We, E_CH, REWEIGHT);

    prop256x_kernel<<<NNODES, 256>>>(b1);
    prop256e_kernel<<<dim3(NNODES, NB_E), 128>>>(be);

    wproj_kernel<<<9, 256>>>(We, be, Wmu, Wsig);
    midproj_kernel<<<2560 + 512, 256>>>(e_noise, Wmu, Wsig);
    tmid_kernel<<<2560, 256>>>();
    prop32_kernel<<<2560, 256>>>(bmu, bsig, out);

    zfin_kernel<<<NB_Z * NNODES * OUTD / 256, 256>>>(eps, rk_lgt, out);

    adj_kernel<<<dim3(32, 32, NB_Z), 256>>>(out);
}